// round 2
// baseline (speedup 1.0000x reference)
#include <cuda_runtime.h>

#define BB 8
#define CC 256
#define NN 4096   // 64*64 tokens
#define GG 32

// Scratch (allocation-free: __device__ globals)
__device__ float g_h[(size_t)BB * CC * NN];          // 33.5 MB  normalized x
__device__ float g_qkv[(size_t)BB * 3 * CC * NN];    // 100.7 MB q,k,v
__device__ float g_S[(size_t)BB * NN * NN];          // 536.9 MB attention scores/probs
__device__ float g_O[(size_t)BB * CC * NN];          // 33.5 MB  attn output

// ---------------------------------------------------------------------------
// GroupNorm: one block per (batch, group). 8 channels * 4096 px = 32768 elems.
// ---------------------------------------------------------------------------
__global__ __launch_bounds__(256) void gn_kernel(const float* __restrict__ x,
                                                 const float* __restrict__ w,
                                                 const float* __restrict__ b,
                                                 float* __restrict__ h) {
    int bg = blockIdx.x;
    int batch = bg >> 5, g = bg & 31;
    size_t base = ((size_t)batch * CC + (size_t)g * 8) * NN;
    const float4* x4 = (const float4*)(x + base);
    float4* h4 = (float4*)(h + base);
    int t = threadIdx.x;

    float s = 0.f, ss = 0.f;
    for (int i = t; i < 8192; i += 256) {
        float4 v = x4[i];
        s  += v.x + v.y + v.z + v.w;
        ss += v.x * v.x + v.y * v.y + v.z * v.z + v.w * v.w;
    }
    __shared__ float rs[8], rq[8];
    #pragma unroll
    for (int o = 16; o; o >>= 1) {
        s  += __shfl_xor_sync(0xffffffffu, s, o);
        ss += __shfl_xor_sync(0xffffffffu, ss, o);
    }
    if ((t & 31) == 0) { rs[t >> 5] = s; rq[t >> 5] = ss; }
    __syncthreads();
    if (t == 0) {
        float a = 0.f, c = 0.f;
        #pragma unroll
        for (int i = 0; i < 8; i++) { a += rs[i]; c += rq[i]; }
        rs[0] = a; rq[0] = c;
    }
    __syncthreads();
    float mu  = rs[0] * (1.f / 32768.f);
    float var = rq[0] * (1.f / 32768.f) - mu * mu;
    float rstd = rsqrtf(var + 1e-5f);

    for (int i = t; i < 8192; i += 256) {
        int c = (g << 3) + (i >> 10);           // 1024 float4 per channel
        float gw = w[c] * rstd;
        float gb = b[c] - mu * gw;
        float4 v = x4[i];
        v.x = v.x * gw + gb; v.y = v.y * gw + gb;
        v.z = v.z * gw + gb; v.w = v.w * gw + gb;
        h4[i] = v;
    }
}

// ---------------------------------------------------------------------------
// Generic 128x128x8 SGEMM, 256 threads, 8x8 micro-tile.
// TA==0: A[m*lda+k]  TA==1: A[k*lda+m]
// TB==0: B[k*ldb+n]  TB==1: B[n*ldb+k]
// C[m*ldc+n] = alpha * sum_k A*B (+ bias[m]) (+ res[m*ldc+n])
// M,N multiples of 128; K multiple of 8.
// ---------------------------------------------------------------------------
template <int TA, int TB, bool HAS_BIAS, bool HAS_RES>
__global__ __launch_bounds__(256) void gemm128(
    const float* __restrict__ A, const float* __restrict__ B,
    const float* __restrict__ bias, const float* __restrict__ res,
    float* __restrict__ C,
    int M, int N, int K, int lda, int ldb, int ldc,
    long long sA, long long sB, long long sRes, long long sC, float alpha) {
    __shared__ float As[8][128];
    __shared__ float Bs[8][128];

    int bz = blockIdx.z;
    A += (size_t)bz * sA;
    B += (size_t)bz * sB;
    C += (size_t)bz * sC;
    if (HAS_RES) res += (size_t)bz * sRes;

    int m0 = blockIdx.y * 128;
    int n0 = blockIdx.x * 128;
    int t = threadIdx.x;
    int tx = t & 15, ty = t >> 4;

    float acc[8][8];
    #pragma unroll
    for (int i = 0; i < 8; i++)
        #pragma unroll
        for (int j = 0; j < 8; j++) acc[i][j] = 0.f;

    for (int k0 = 0; k0 < K; k0 += 8) {
        if (TA == 1) {
            int kk = t >> 5, mm = (t & 31) * 4;
            float4 v = *(const float4*)&A[(size_t)(k0 + kk) * lda + m0 + mm];
            *(float4*)&As[kk][mm] = v;
        } else {
            int mm = t >> 1, kk = (t & 1) * 4;
            float4 v = *(const float4*)&A[(size_t)(m0 + mm) * lda + k0 + kk];
            As[kk + 0][mm] = v.x; As[kk + 1][mm] = v.y;
            As[kk + 2][mm] = v.z; As[kk + 3][mm] = v.w;
        }
        if (TB == 0) {
            int kk = t >> 5, nn = (t & 31) * 4;
            float4 v = *(const float4*)&B[(size_t)(k0 + kk) * ldb + n0 + nn];
            *(float4*)&Bs[kk][nn] = v;
        } else {
            int nn = t >> 1, kk = (t & 1) * 4;
            float4 v = *(const float4*)&B[(size_t)(n0 + nn) * ldb + k0 + kk];
            Bs[kk + 0][nn] = v.x; Bs[kk + 1][nn] = v.y;
            Bs[kk + 2][nn] = v.z; Bs[kk + 3][nn] = v.w;
        }
        __syncthreads();
        #pragma unroll
        for (int kk = 0; kk < 8; kk++) {
            float4 a0 = *(const float4*)&As[kk][ty * 4];
            float4 a1 = *(const float4*)&As[kk][64 + ty * 4];
            float4 b0 = *(const float4*)&Bs[kk][tx * 4];
            float4 b1 = *(const float4*)&Bs[kk][64 + tx * 4];
            float av[8] = {a0.x, a0.y, a0.z, a0.w, a1.x, a1.y, a1.z, a1.w};
            float bv[8] = {b0.x, b0.y, b0.z, b0.w, b1.x, b1.y, b1.z, b1.w};
            #pragma unroll
            for (int i = 0; i < 8; i++)
                #pragma unroll
                for (int j = 0; j < 8; j++) acc[i][j] += av[i] * bv[j];
        }
        __syncthreads();
    }

    #pragma unroll
    for (int i = 0; i < 8; i++) {
        int m = m0 + ((i < 4) ? (ty * 4 + i) : (64 + ty * 4 + i - 4));
        float bval = HAS_BIAS ? bias[m] : 0.f;
        float* crow = C + (size_t)m * ldc;
        const float* rrow = HAS_RES ? (res + (size_t)m * ldc) : (const float*)0;
        float4 o0, o1;
        o0.x = alpha * acc[i][0] + bval; o0.y = alpha * acc[i][1] + bval;
        o0.z = alpha * acc[i][2] + bval; o0.w = alpha * acc[i][3] + bval;
        o1.x = alpha * acc[i][4] + bval; o1.y = alpha * acc[i][5] + bval;
        o1.z = alpha * acc[i][6] + bval; o1.w = alpha * acc[i][7] + bval;
        int c0 = n0 + tx * 4;
        int c1 = n0 + 64 + tx * 4;
        if (HAS_RES) {
            float4 r0 = *(const float4*)&rrow[c0];
            float4 r1 = *(const float4*)&rrow[c1];
            o0.x += r0.x; o0.y += r0.y; o0.z += r0.z; o0.w += r0.w;
            o1.x += r1.x; o1.y += r1.y; o1.z += r1.z; o1.w += r1.w;
        }
        *(float4*)&crow[c0] = o0;
        *(float4*)&crow[c1] = o1;
    }
}

// ---------------------------------------------------------------------------
// Row softmax over S rows of length 4096. One block (256 thr) per row.
// Entire row lives in registers (16 floats/thread): 1 read + 1 write.
// ---------------------------------------------------------------------------
__global__ __launch_bounds__(256) void softmax_kernel(float* __restrict__ S) {
    size_t row = blockIdx.x;
    float4* p = (float4*)(S + row * (size_t)NN);
    int t = threadIdx.x;
    float4 v[4];
    float mx = -1e30f;
    #pragma unroll
    for (int i = 0; i < 4; i++) {
        v[i] = p[i * 256 + t];
        mx = fmaxf(mx, fmaxf(fmaxf(v[i].x, v[i].y), fmaxf(v[i].z, v[i].w)));
    }
    __shared__ float red[8];
    #pragma unroll
    for (int o = 16; o; o >>= 1) mx = fmaxf(mx, __shfl_xor_sync(0xffffffffu, mx, o));
    if ((t & 31) == 0) red[t >> 5] = mx;
    __syncthreads();
    if (t == 0) {
        float a = red[0];
        #pragma unroll
        for (int i = 1; i < 8; i++) a = fmaxf(a, red[i]);
        red[0] = a;
    }
    __syncthreads();
    mx = red[0];
    __syncthreads();

    float sum = 0.f;
    #pragma unroll
    for (int i = 0; i < 4; i++) {
        v[i].x = __expf(v[i].x - mx); v[i].y = __expf(v[i].y - mx);
        v[i].z = __expf(v[i].z - mx); v[i].w = __expf(v[i].w - mx);
        sum += v[i].x + v[i].y + v[i].z + v[i].w;
    }
    #pragma unroll
    for (int o = 16; o; o >>= 1) sum += __shfl_xor_sync(0xffffffffu, sum, o);
    if ((t & 31) == 0) red[t >> 5] = sum;
    __syncthreads();
    if (t == 0) {
        float a = 0.f;
        #pragma unroll
        for (int i = 0; i < 8; i++) a += red[i];
        red[0] = a;
    }
    __syncthreads();
    float inv = 1.f / red[0];
    #pragma unroll
    for (int i = 0; i < 4; i++) {
        v[i].x *= inv; v[i].y *= inv; v[i].z *= inv; v[i].w *= inv;
        p[i * 256 + t] = v[i];
    }
}

// ---------------------------------------------------------------------------
extern "C" void kernel_launch(void* const* d_in, const int* in_sizes, int n_in,
                              void* d_out, int out_size) {
    const float* x  = (const float*)d_in[0];
    const float* nw = (const float*)d_in[1];
    const float* nb = (const float*)d_in[2];
    const float* qw = (const float*)d_in[3];
    const float* qb = (const float*)d_in[4];
    const float* pw = (const float*)d_in[5];
    const float* pb = (const float*)d_in[6];
    float* out = (float*)d_out;

    float *hP, *qkvP, *SP, *OP;
    cudaGetSymbolAddress((void**)&hP, g_h);
    cudaGetSymbolAddress((void**)&qkvP, g_qkv);
    cudaGetSymbolAddress((void**)&SP, g_S);
    cudaGetSymbolAddress((void**)&OP, g_O);

    const long long sCN = (long long)CC * NN;       // 1,048,576
    const long long s3CN = (long long)3 * CC * NN;  // 3,145,728
    const long long sNN = (long long)NN * NN;       // 16,777,216

    // 1) GroupNorm
    gn_kernel<<<BB * GG, 256>>>(x, nw, nb, hP);

    // 2) qkv[b,o,n] = qkv_w[o,c] @ h[b,c,n] + qkv_b[o]
    gemm128<0, 0, true, false><<<dim3(NN / 128, 768 / 128, BB), 256>>>(
        qw, hP, qb, (const float*)0, qkvP,
        768, NN, CC, CC, NN, NN, 0LL, sCN, 0LL, s3CN, 1.f);

    // 3) S[b,i,j] = (1/16) * sum_c q[b,c,i] * k[b,c,j]
    gemm128<1, 0, false, false><<<dim3(NN / 128, NN / 128, BB), 256>>>(
        qkvP, qkvP + (size_t)CC * NN, (const float*)0, (const float*)0, SP,
        NN, NN, CC, NN, NN, NN, s3CN, s3CN, 0LL, sNN, 0.0625f);

    // 4) softmax rows
    softmax_kernel<<<BB * NN, 256>>>(SP);

    // 5) O[b,c,i] = sum_j v[b,c,j] * P[b,i,j]
    gemm128<0, 1, false, false><<<dim3(NN / 128, CC / 128, BB), 256>>>(
        qkvP + (size_t)2 * CC * NN, SP, (const float*)0, (const float*)0, OP,
        CC, NN, NN, NN, NN, NN, s3CN, sNN, 0LL, sCN, 1.f);

    // 6) out = x + proj_w @ O + proj_b
    gemm128<0, 0, true, true><<<dim3(NN / 128, CC / 128, BB), 256>>>(
        pw, OP, pb, x, out,
        CC, NN, CC, CC, NN, NN, 0LL, sCN, sCN, sCN, 1.f);
}

// round 3
// speedup vs baseline: 4.4026x; 4.4026x over previous
#include <cuda_runtime.h>
#include <cuda_bf16.h>
#include <cstdint>

#define BB 8
#define CC 256
#define NN 4096   // 64*64 tokens
#define GG 32

// Scratch (allocation-free: __device__ globals)
__device__ __nv_bfloat16 g_hT[(size_t)BB * NN * CC];    // [b][n][c]      16.8 MB
__device__ __nv_bfloat16 g_qkT[(size_t)BB * NN * 512];  // [b][n][q|k]    33.5 MB
__device__ __nv_bfloat16 g_v[(size_t)BB * CC * NN];     // [b][c][n]      16.8 MB
__device__ float         g_S[(size_t)BB * NN * NN];     // logits fp32   536.9 MB
__device__ __nv_bfloat16 g_P[(size_t)BB * NN * NN];     // probs bf16    268.4 MB
__device__ float         g_O[(size_t)BB * CC * NN];     // attn out fp32  33.5 MB
__device__ __nv_bfloat16 g_wb[768 * 256];               // qkv_w bf16

// ---------------------------------------------------------------------------
__global__ void cvt_w_kernel(const float* __restrict__ w, __nv_bfloat16* __restrict__ o, int n) {
    int i = blockIdx.x * 256 + threadIdx.x;
    if (i < n) o[i] = __float2bfloat16(w[i]);
}

// ---------------------------------------------------------------------------
// GroupNorm: one block per (batch, group). Writes hT bf16 [n, c].
// ---------------------------------------------------------------------------
__global__ __launch_bounds__(256) void gn_kernel(const float* __restrict__ x,
                                                 const float* __restrict__ w,
                                                 const float* __restrict__ b,
                                                 __nv_bfloat16* __restrict__ hT) {
    int bg = blockIdx.x;
    int batch = bg >> 5, g = bg & 31;
    size_t base = ((size_t)batch * CC + (size_t)g * 8) * NN;
    const float4* x4 = (const float4*)(x + base);
    int t = threadIdx.x;

    float s = 0.f, ss = 0.f;
    for (int i = t; i < 8192; i += 256) {
        float4 v = x4[i];
        s  += v.x + v.y + v.z + v.w;
        ss += v.x * v.x + v.y * v.y + v.z * v.z + v.w * v.w;
    }
    __shared__ float rs[8], rq[8];
    #pragma unroll
    for (int o = 16; o; o >>= 1) {
        s  += __shfl_xor_sync(0xffffffffu, s, o);
        ss += __shfl_xor_sync(0xffffffffu, ss, o);
    }
    if ((t & 31) == 0) { rs[t >> 5] = s; rq[t >> 5] = ss; }
    __syncthreads();
    if (t == 0) {
        float a = 0.f, c = 0.f;
        #pragma unroll
        for (int i = 0; i < 8; i++) { a += rs[i]; c += rq[i]; }
        rs[0] = a; rq[0] = c;
    }
    __syncthreads();
    float mu  = rs[0] * (1.f / 32768.f);
    float var = rq[0] * (1.f / 32768.f) - mu * mu;
    float rstd = rsqrtf(var + 1e-5f);

    float gw[8], gb[8];
    #pragma unroll
    for (int cc = 0; cc < 8; cc++) {
        int c = (g << 3) + cc;
        gw[cc] = w[c] * rstd;
        gb[cc] = b[c] - mu * gw[cc];
    }

    const float* xs = x + base;
    __nv_bfloat16* ho = hT + (size_t)batch * NN * CC + g * 8;
    for (int n = t; n < NN; n += 256) {
        __nv_bfloat162 pk[4];
        #pragma unroll
        for (int cc = 0; cc < 8; cc += 2) {
            float v0 = xs[(size_t)cc * NN + n] * gw[cc] + gb[cc];
            float v1 = xs[(size_t)(cc + 1) * NN + n] * gw[cc + 1] + gb[cc + 1];
            pk[cc >> 1] = __floats2bfloat162_rn(v0, v1);
        }
        uint4 u;
        u.x = *(uint32_t*)&pk[0]; u.y = *(uint32_t*)&pk[1];
        u.z = *(uint32_t*)&pk[2]; u.w = *(uint32_t*)&pk[3];
        *(uint4*)&ho[(size_t)n * CC] = u;
    }
}

// ---------------------------------------------------------------------------
// bf16 TN MMA GEMM: C = alpha * A * B^T  (A[M,K] row-major, B[N,K] row-major)
// 128x128 block tile, k-tile 32, 8 warps (4x2), warp tile 32x64, m16n8k16.
// OUTMODE 0: fp32 C[m*ldc+n]
// OUTMODE 1: qkv special: val+bias[m]; m<512 -> qkT[n*512+m] bf16 (transposed),
//            m>=512 -> vout[(m-512)*NN+n] bf16
// ---------------------------------------------------------------------------
__device__ __forceinline__ uint32_t s2u(const void* p) {
    return (uint32_t)__cvta_generic_to_shared(p);
}
__device__ __forceinline__ void cp16(void* smem, const void* g) {
    asm volatile("cp.async.cg.shared.global [%0], [%1], 16;\n"
                 :: "r"(s2u(smem)), "l"(g));
}
__device__ __forceinline__ void cp_commit() { asm volatile("cp.async.commit_group;\n"); }
template <int N_>
__device__ __forceinline__ void cp_wait() { asm volatile("cp.async.wait_group %0;\n" :: "n"(N_)); }

__device__ __forceinline__ void ldsm4(uint32_t& r0, uint32_t& r1, uint32_t& r2, uint32_t& r3,
                                      uint32_t addr) {
    asm volatile("ldmatrix.sync.aligned.m8n8.x4.shared.b16 {%0,%1,%2,%3}, [%4];\n"
                 : "=r"(r0), "=r"(r1), "=r"(r2), "=r"(r3) : "r"(addr));
}
__device__ __forceinline__ void mma16816(float* c, const uint32_t* a, const uint32_t* b) {
    asm volatile(
        "mma.sync.aligned.m16n8k16.row.col.f32.bf16.bf16.f32 "
        "{%0,%1,%2,%3}, {%4,%5,%6,%7}, {%8,%9}, {%0,%1,%2,%3};\n"
        : "+f"(c[0]), "+f"(c[1]), "+f"(c[2]), "+f"(c[3])
        : "r"(a[0]), "r"(a[1]), "r"(a[2]), "r"(a[3]), "r"(b[0]), "r"(b[1]));
}

#define SPITCH 40  // 32 bf16 + 8 pad (16B-aligned rows, conflict-free ldmatrix)

template <int OUTMODE>
__global__ __launch_bounds__(256, 2) void mma_gemm(
    const __nv_bfloat16* __restrict__ A, const __nv_bfloat16* __restrict__ B,
    const float* __restrict__ bias, float* __restrict__ Cf,
    __nv_bfloat16* __restrict__ out_qk, __nv_bfloat16* __restrict__ out_v,
    int M, int N, int K, int lda, int ldb, int ldc,
    long long sA, long long sB, long long sC, float alpha) {
    __shared__ __nv_bfloat16 sAt[2][128 * SPITCH];
    __shared__ __nv_bfloat16 sBt[2][128 * SPITCH];

    int bz = blockIdx.z;
    A += (size_t)bz * sA;
    B += (size_t)bz * sB;
    if (OUTMODE == 0) Cf += (size_t)bz * sC;
    else {
        out_qk += (size_t)bz * ((long long)NN * 512);
        out_v  += (size_t)bz * ((long long)CC * NN);
    }

    int m0 = blockIdx.y * 128;
    int n0 = blockIdx.x * 128;
    int t = threadIdx.x;
    int lane = t & 31;
    int wid = t >> 5;
    int wm0 = (wid & 3) * 32;
    int wn0 = (wid >> 2) * 64;

    float acc[2][8][4];
    #pragma unroll
    for (int mi = 0; mi < 2; mi++)
        #pragma unroll
        for (int ni = 0; ni < 8; ni++)
            #pragma unroll
            for (int j = 0; j < 4; j++) acc[mi][ni][j] = 0.f;

    int ktot = K >> 5;

    // stage loader: 4 cp.async per thread
    int lrow0 = t >> 2;
    int lch = (t & 3) * 8;

    {   // stage 0
        #pragma unroll
        for (int p = 0; p < 2; p++) {
            int row = lrow0 + p * 64;
            cp16(&sAt[0][row * SPITCH + lch], A + (size_t)(m0 + row) * lda + lch);
            cp16(&sBt[0][row * SPITCH + lch], B + (size_t)(n0 + row) * ldb + lch);
        }
        cp_commit();
    }

    for (int kt = 0; kt < ktot; kt++) {
        int buf = kt & 1;
        if (kt + 1 < ktot) {
            int nb = buf ^ 1;
            int k0 = (kt + 1) << 5;
            #pragma unroll
            for (int p = 0; p < 2; p++) {
                int row = lrow0 + p * 64;
                cp16(&sAt[nb][row * SPITCH + lch], A + (size_t)(m0 + row) * lda + k0 + lch);
                cp16(&sBt[nb][row * SPITCH + lch], B + (size_t)(n0 + row) * ldb + k0 + lch);
            }
            cp_commit();
            cp_wait<1>();
        } else {
            cp_wait<0>();
        }
        __syncthreads();

        uint32_t baseA = s2u(&sAt[buf][0]);
        uint32_t baseB = s2u(&sBt[buf][0]);
        #pragma unroll
        for (int h = 0; h < 2; h++) {
            int kk = h * 16;
            uint32_t a[2][4];
            #pragma unroll
            for (int mi = 0; mi < 2; mi++) {
                int row = wm0 + mi * 16 + (lane & 15);
                int col = kk + ((lane >> 4) << 3);
                ldsm4(a[mi][0], a[mi][1], a[mi][2], a[mi][3],
                      baseA + (row * SPITCH + col) * 2);
            }
            uint32_t bf[8][2];
            #pragma unroll
            for (int nj = 0; nj < 4; nj++) {
                int seg = lane >> 3, r = lane & 7;
                int n = wn0 + nj * 16 + ((seg >> 1) << 3) + r;
                int col = kk + ((seg & 1) << 3);
                uint32_t r0, r1, r2, r3;
                ldsm4(r0, r1, r2, r3, baseB + (n * SPITCH + col) * 2);
                bf[2 * nj][0] = r0; bf[2 * nj][1] = r1;
                bf[2 * nj + 1][0] = r2; bf[2 * nj + 1][1] = r3;
            }
            #pragma unroll
            for (int mi = 0; mi < 2; mi++)
                #pragma unroll
                for (int ni = 0; ni < 8; ni++)
                    mma16816(acc[mi][ni], a[mi], bf[ni]);
        }
        __syncthreads();
    }

    // epilogue
    #pragma unroll
    for (int mi = 0; mi < 2; mi++) {
        int r0 = m0 + wm0 + mi * 16 + (lane >> 2);
        float b0 = 0.f, b8 = 0.f;
        if (OUTMODE == 1) { b0 = bias[r0]; b8 = bias[r0 + 8]; }
        #pragma unroll
        for (int ni = 0; ni < 8; ni++) {
            int c = n0 + wn0 + ni * 8 + 2 * (lane & 3);
            if (OUTMODE == 0) {
                float2 v01 = make_float2(alpha * acc[mi][ni][0], alpha * acc[mi][ni][1]);
                float2 v23 = make_float2(alpha * acc[mi][ni][2], alpha * acc[mi][ni][3]);
                *(float2*)&Cf[(size_t)r0 * ldc + c] = v01;
                *(float2*)&Cf[(size_t)(r0 + 8) * ldc + c] = v23;
            } else {
                float v0 = acc[mi][ni][0] + b0;
                float v1 = acc[mi][ni][1] + b0;
                float v2 = acc[mi][ni][2] + b8;
                float v3 = acc[mi][ni][3] + b8;
                if (r0 < 512) {
                    out_qk[(size_t)c * 512 + r0] = __float2bfloat16(v0);
                    out_qk[(size_t)(c + 1) * 512 + r0] = __float2bfloat16(v1);
                    out_qk[(size_t)c * 512 + r0 + 8] = __float2bfloat16(v2);
                    out_qk[(size_t)(c + 1) * 512 + r0 + 8] = __float2bfloat16(v3);
                } else {
                    *(__nv_bfloat162*)&out_v[(size_t)(r0 - 512) * NN + c] =
                        __floats2bfloat162_rn(v0, v1);
                    *(__nv_bfloat162*)&out_v[(size_t)(r0 - 512 + 8) * NN + c] =
                        __floats2bfloat162_rn(v2, v3);
                }
            }
        }
    }
}

// ---------------------------------------------------------------------------
// fp32 gemm128 (kept for the small proj gemm: bias + residual epilogue)
// ---------------------------------------------------------------------------
template <int TA, int TB, bool HAS_BIAS, bool HAS_RES>
__global__ __launch_bounds__(256) void gemm128(
    const float* __restrict__ A, const float* __restrict__ B,
    const float* __restrict__ bias, const float* __restrict__ res,
    float* __restrict__ C,
    int M, int N, int K, int lda, int ldb, int ldc,
    long long sA, long long sB, long long sRes, long long sC, float alpha) {
    __shared__ float As[8][128];
    __shared__ float Bs[8][128];

    int bz = blockIdx.z;
    A += (size_t)bz * sA;
    B += (size_t)bz * sB;
    C += (size_t)bz * sC;
    if (HAS_RES) res += (size_t)bz * sRes;

    int m0 = blockIdx.y * 128;
    int n0 = blockIdx.x * 128;
    int t = threadIdx.x;
    int tx = t & 15, ty = t >> 4;

    float acc[8][8];
    #pragma unroll
    for (int i = 0; i < 8; i++)
        #pragma unroll
        for (int j = 0; j < 8; j++) acc[i][j] = 0.f;

    for (int k0 = 0; k0 < K; k0 += 8) {
        if (TA == 1) {
            int kk = t >> 5, mm = (t & 31) * 4;
            float4 v = *(const float4*)&A[(size_t)(k0 + kk) * lda + m0 + mm];
            *(float4*)&As[kk][mm] = v;
        } else {
            int mm = t >> 1, kk = (t & 1) * 4;
            float4 v = *(const float4*)&A[(size_t)(m0 + mm) * lda + k0 + kk];
            As[kk + 0][mm] = v.x; As[kk + 1][mm] = v.y;
            As[kk + 2][mm] = v.z; As[kk + 3][mm] = v.w;
        }
        if (TB == 0) {
            int kk = t >> 5, nn = (t & 31) * 4;
            float4 v = *(const float4*)&B[(size_t)(k0 + kk) * ldb + n0 + nn];
            *(float4*)&Bs[kk][nn] = v;
        } else {
            int nn = t >> 1, kk = (t & 1) * 4;
            float4 v = *(const float4*)&B[(size_t)(n0 + nn) * ldb + k0 + kk];
            Bs[kk + 0][nn] = v.x; Bs[kk + 1][nn] = v.y;
            Bs[kk + 2][nn] = v.z; Bs[kk + 3][nn] = v.w;
        }
        __syncthreads();
        #pragma unroll
        for (int kk = 0; kk < 8; kk++) {
            float4 a0 = *(const float4*)&As[kk][ty * 4];
            float4 a1 = *(const float4*)&As[kk][64 + ty * 4];
            float4 b0 = *(const float4*)&Bs[kk][tx * 4];
            float4 b1 = *(const float4*)&Bs[kk][64 + tx * 4];
            float av[8] = {a0.x, a0.y, a0.z, a0.w, a1.x, a1.y, a1.z, a1.w};
            float bv[8] = {b0.x, b0.y, b0.z, b0.w, b1.x, b1.y, b1.z, b1.w};
            #pragma unroll
            for (int i = 0; i < 8; i++)
                #pragma unroll
                for (int j = 0; j < 8; j++) acc[i][j] += av[i] * bv[j];
        }
        __syncthreads();
    }

    #pragma unroll
    for (int i = 0; i < 8; i++) {
        int m = m0 + ((i < 4) ? (ty * 4 + i) : (64 + ty * 4 + i - 4));
        float bval = HAS_BIAS ? bias[m] : 0.f;
        float* crow = C + (size_t)m * ldc;
        const float* rrow = HAS_RES ? (res + (size_t)m * ldc) : (const float*)0;
        float4 o0, o1;
        o0.x = alpha * acc[i][0] + bval; o0.y = alpha * acc[i][1] + bval;
        o0.z = alpha * acc[i][2] + bval; o0.w = alpha * acc[i][3] + bval;
        o1.x = alpha * acc[i][4] + bval; o1.y = alpha * acc[i][5] + bval;
        o1.z = alpha * acc[i][6] + bval; o1.w = alpha * acc[i][7] + bval;
        int c0 = n0 + tx * 4;
        int c1 = n0 + 64 + tx * 4;
        if (HAS_RES) {
            float4 r0 = *(const float4*)&rrow[c0];
            float4 r1 = *(const float4*)&rrow[c1];
            o0.x += r0.x; o0.y += r0.y; o0.z += r0.z; o0.w += r0.w;
            o1.x += r1.x; o1.y += r1.y; o1.z += r1.z; o1.w += r1.w;
        }
        *(float4*)&crow[c0] = o0;
        *(float4*)&crow[c1] = o1;
    }
}

// ---------------------------------------------------------------------------
// Row softmax: fp32 logits in, bf16 probs out. One block per row.
// ---------------------------------------------------------------------------
__global__ __launch_bounds__(256) void softmax_kernel(const float* __restrict__ S,
                                                      __nv_bfloat16* __restrict__ P) {
    size_t row = blockIdx.x;
    const float4* p = (const float4*)(S + row * (size_t)NN);
    __nv_bfloat16* po = P + row * (size_t)NN;
    int t = threadIdx.x;
    float4 v[4];
    float mx = -1e30f;
    #pragma unroll
    for (int i = 0; i < 4; i++) {
        v[i] = p[i * 256 + t];
        mx = fmaxf(mx, fmaxf(fmaxf(v[i].x, v[i].y), fmaxf(v[i].z, v[i].w)));
    }
    __shared__ float red[8];
    #pragma unroll
    for (int o = 16; o; o >>= 1) mx = fmaxf(mx, __shfl_xor_sync(0xffffffffu, mx, o));
    if ((t & 31) == 0) red[t >> 5] = mx;
    __syncthreads();
    if (t == 0) {
        float a = red[0];
        #pragma unroll
        for (int i = 1; i < 8; i++) a = fmaxf(a, red[i]);
        red[0] = a;
    }
    __syncthreads();
    mx = red[0];
    __syncthreads();

    float sum = 0.f;
    #pragma unroll
    for (int i = 0; i < 4; i++) {
        v[i].x = __expf(v[i].x - mx); v[i].y = __expf(v[i].y - mx);
        v[i].z = __expf(v[i].z - mx); v[i].w = __expf(v[i].w - mx);
        sum += v[i].x + v[i].y + v[i].z + v[i].w;
    }
    #pragma unroll
    for (int o = 16; o; o >>= 1) sum += __shfl_xor_sync(0xffffffffu, sum, o);
    if ((t & 31) == 0) red[t >> 5] = sum;
    __syncthreads();
    if (t == 0) {
        float a = 0.f;
        #pragma unroll
        for (int i = 0; i < 8; i++) a += red[i];
        red[0] = a;
    }
    __syncthreads();
    float inv = 1.f / red[0];
    #pragma unroll
    for (int i = 0; i < 4; i++) {
        __nv_bfloat162 p0 = __floats2bfloat162_rn(v[i].x * inv, v[i].y * inv);
        __nv_bfloat162 p1 = __floats2bfloat162_rn(v[i].z * inv, v[i].w * inv);
        uint2 u;
        u.x = *(uint32_t*)&p0; u.y = *(uint32_t*)&p1;
        *(uint2*)&po[i * 1024 + t * 4] = u;
    }
}

// ---------------------------------------------------------------------------
extern "C" void kernel_launch(void* const* d_in, const int* in_sizes, int n_in,
                              void* d_out, int out_size) {
    const float* x  = (const float*)d_in[0];
    const float* nw = (const float*)d_in[1];
    const float* nb = (const float*)d_in[2];
    const float* qw = (const float*)d_in[3];
    const float* qb = (const float*)d_in[4];
    const float* pw = (const float*)d_in[5];
    const float* pb = (const float*)d_in[6];
    float* out = (float*)d_out;

    __nv_bfloat16 *hTP, *qkTP, *vP, *PP, *wbP;
    float *SP, *OP;
    cudaGetSymbolAddress((void**)&hTP, g_hT);
    cudaGetSymbolAddress((void**)&qkTP, g_qkT);
    cudaGetSymbolAddress((void**)&vP, g_v);
    cudaGetSymbolAddress((void**)&SP, g_S);
    cudaGetSymbolAddress((void**)&PP, g_P);
    cudaGetSymbolAddress((void**)&OP, g_O);
    cudaGetSymbolAddress((void**)&wbP, g_wb);

    const long long sCN  = (long long)CC * NN;
    const long long sNC  = (long long)NN * CC;
    const long long sNQK = (long long)NN * 512;
    const long long sNN2 = (long long)NN * NN;

    // 0) qkv weights -> bf16
    cvt_w_kernel<<<768, 256>>>(qw, wbP, 768 * 256);

    // 1) GroupNorm -> hT bf16 [n, c]
    gn_kernel<<<BB * GG, 256>>>(x, nw, nb, hTP);

    // 2) qkv = qkv_w @ h + b  -> qkT bf16 [n, 512], v bf16 [c, n]
    mma_gemm<1><<<dim3(NN / 128, 768 / 128, BB), 256>>>(
        wbP, hTP, qb, (float*)0, qkTP, vP,
        768, NN, CC, CC, CC, 0, 0LL, sNC, 0LL, 1.f);

    // 3) S = (1/16) q^T k   (A = qkT[:, :256], B = qkT[:, 256:], TN)
    mma_gemm<0><<<dim3(NN / 128, NN / 128, BB), 256>>>(
        qkTP, qkTP + 256, (const float*)0, SP, (__nv_bfloat16*)0, (__nv_bfloat16*)0,
        NN, NN, CC, 512, 512, NN, sNQK, sNQK, sNN2, 0.0625f);

    // 4) softmax rows -> P bf16
    softmax_kernel<<<BB * NN, 256>>>(SP, PP);

    // 5) O = V @ P^T  (A = v [c, n_k], B = P [n_q, n_k], TN) -> fp32 [c, n]
    mma_gemm<0><<<dim3(NN / 128, CC / 128, BB), 256>>>(
        vP, PP, (const float*)0, OP, (__nv_bfloat16*)0, (__nv_bfloat16*)0,
        CC, NN, NN, NN, NN, NN, sCN, sNN2, sCN, 1.f);

    // 6) out = x + proj_w @ O + proj_b  (fp32)
    gemm128<0, 0, true, true><<<dim3(NN / 128, CC / 128, BB), 256>>>(
        pw, OP, pb, x, out,
        CC, NN, CC, CC, NN, NN, 0LL, sCN, sCN, sCN, 1.f);
}

// round 6
// speedup vs baseline: 6.3842x; 1.4501x over previous
#include <cuda_runtime.h>
#include <cuda_bf16.h>
#include <cstdint>

#define BB 8
#define CC 256
#define NN 4096
#define GG 32

#define TQ 128
#define TK 64
#define QP 264     // 256 + 8 pad (bf16), row stride 528B -> conflict-free ldmatrix
#define VP 72      // 64 + 8 pad
#define NIT (NN / TK)

// Scratch (allocation-free __device__ globals)
__device__ __nv_bfloat16 g_hT[(size_t)BB * NN * CC];     // [b][n][c]
__device__ __nv_bfloat16 g_qkT[(size_t)BB * NN * 512];   // [b][n][q(256)|k(256)]
__device__ __nv_bfloat16 g_v[(size_t)BB * CC * NN];      // [b][c][n]
__device__ __nv_bfloat16 g_Ob[(size_t)BB * NN * CC];     // [b][n][c] attn out bf16
__device__ __nv_bfloat16 g_wqkv[768 * 256];
__device__ __nv_bfloat16 g_wproj[256 * 256];

// ---------------------------------------------------------------------------
__global__ void cvt_w_kernel(const float* __restrict__ w, __nv_bfloat16* __restrict__ o, int n) {
    int i = blockIdx.x * 256 + threadIdx.x;
    if (i < n) o[i] = __float2bfloat16(w[i]);
}

// ---------------------------------------------------------------------------
// GroupNorm -> hT bf16 [n, c]
// ---------------------------------------------------------------------------
__global__ __launch_bounds__(256) void gn_kernel(const float* __restrict__ x,
                                                 const float* __restrict__ w,
                                                 const float* __restrict__ b,
                                                 __nv_bfloat16* __restrict__ hT) {
    int bg = blockIdx.x;
    int batch = bg >> 5, g = bg & 31;
    size_t base = ((size_t)batch * CC + (size_t)g * 8) * NN;
    const float4* x4 = (const float4*)(x + base);
    int t = threadIdx.x;

    float s = 0.f, ss = 0.f;
    for (int i = t; i < 8192; i += 256) {
        float4 v = x4[i];
        s  += v.x + v.y + v.z + v.w;
        ss += v.x * v.x + v.y * v.y + v.z * v.z + v.w * v.w;
    }
    __shared__ float rs[8], rq[8];
    #pragma unroll
    for (int o = 16; o; o >>= 1) {
        s  += __shfl_xor_sync(0xffffffffu, s, o);
        ss += __shfl_xor_sync(0xffffffffu, ss, o);
    }
    if ((t & 31) == 0) { rs[t >> 5] = s; rq[t >> 5] = ss; }
    __syncthreads();
    if (t == 0) {
        float a = 0.f, c = 0.f;
        #pragma unroll
        for (int i = 0; i < 8; i++) { a += rs[i]; c += rq[i]; }
        rs[0] = a; rq[0] = c;
    }
    __syncthreads();
    float mu  = rs[0] * (1.f / 32768.f);
    float var = rq[0] * (1.f / 32768.f) - mu * mu;
    float rstd = rsqrtf(var + 1e-5f);

    float gw[8], gb[8];
    #pragma unroll
    for (int cc = 0; cc < 8; cc++) {
        int c = (g << 3) + cc;
        gw[cc] = w[c] * rstd;
        gb[cc] = b[c] - mu * gw[cc];
    }

    const float* xs = x + base;
    __nv_bfloat16* ho = hT + (size_t)batch * NN * CC + g * 8;
    for (int n = t; n < NN; n += 256) {
        __nv_bfloat162 pk[4];
        #pragma unroll
        for (int cc = 0; cc < 8; cc += 2) {
            float v0 = xs[(size_t)cc * NN + n] * gw[cc] + gb[cc];
            float v1 = xs[(size_t)(cc + 1) * NN + n] * gw[cc + 1] + gb[cc + 1];
            pk[cc >> 1] = __floats2bfloat162_rn(v0, v1);
        }
        uint4 u;
        u.x = *(uint32_t*)&pk[0]; u.y = *(uint32_t*)&pk[1];
        u.z = *(uint32_t*)&pk[2]; u.w = *(uint32_t*)&pk[3];
        *(uint4*)&ho[(size_t)n * CC] = u;
    }
}

// ---------------------------------------------------------------------------
// MMA helpers
// ---------------------------------------------------------------------------
__device__ __forceinline__ uint32_t s2u(const void* p) {
    return (uint32_t)__cvta_generic_to_shared(p);
}
__device__ __forceinline__ void cp16(void* smem, const void* g) {
    asm volatile("cp.async.cg.shared.global [%0], [%1], 16;\n"
                 :: "r"(s2u(smem)), "l"(g));
}
__device__ __forceinline__ void cp_commit() { asm volatile("cp.async.commit_group;\n"); }
template <int N_>
__device__ __forceinline__ void cp_wait() { asm volatile("cp.async.wait_group %0;\n" :: "n"(N_)); }

__device__ __forceinline__ void ldsm4(uint32_t& r0, uint32_t& r1, uint32_t& r2, uint32_t& r3,
                                      uint32_t addr) {
    asm volatile("ldmatrix.sync.aligned.m8n8.x4.shared.b16 {%0,%1,%2,%3}, [%4];\n"
                 : "=r"(r0), "=r"(r1), "=r"(r2), "=r"(r3) : "r"(addr));
}
__device__ __forceinline__ void mma16816(float* c, const uint32_t* a, const uint32_t* b) {
    asm volatile(
        "mma.sync.aligned.m16n8k16.row.col.f32.bf16.bf16.f32 "
        "{%0,%1,%2,%3}, {%4,%5,%6,%7}, {%8,%9}, {%0,%1,%2,%3};\n"
        : "+f"(c[0]), "+f"(c[1]), "+f"(c[2]), "+f"(c[3])
        : "r"(a[0]), "r"(a[1]), "r"(a[2]), "r"(a[3]), "r"(b[0]), "r"(b[1]));
}
__device__ __forceinline__ uint32_t packbf(float a, float b) {
    __nv_bfloat162 p = __floats2bfloat162_rn(a, b);
    return *(uint32_t*)&p;
}

// ---------------------------------------------------------------------------
// bf16 TN MMA GEMM (128x128 tile, ktile 32, 8 warps, warp 32x64)
// OUTMODE 1: qkv: +bias[m]; m<512 -> qkT[n*512+m], m>=512 -> v[(m-512)*NN+n]
// OUTMODE 2: proj: Cf[m*ldc+n] = acc + bias[m] + res[m*ldc+n]  (fp32)
// ---------------------------------------------------------------------------
#define SPITCH 40

template <int OUTMODE>
__global__ __launch_bounds__(256, 2) void mma_gemm(
    const __nv_bfloat16* __restrict__ A, const __nv_bfloat16* __restrict__ B,
    const float* __restrict__ bias, const float* __restrict__ res,
    float* __restrict__ Cf,
    __nv_bfloat16* __restrict__ out_qk, __nv_bfloat16* __restrict__ out_v,
    int M, int N, int K, int lda, int ldb, int ldc,
    long long sA, long long sB, long long sRes, long long sC) {
    __shared__ __nv_bfloat16 sAt[2][128 * SPITCH];
    __shared__ __nv_bfloat16 sBt[2][128 * SPITCH];

    int bz = blockIdx.z;
    A += (size_t)bz * sA;
    B += (size_t)bz * sB;
    if (OUTMODE == 2) { Cf += (size_t)bz * sC; res += (size_t)bz * sRes; }
    else {
        out_qk += (size_t)bz * ((long long)NN * 512);
        out_v  += (size_t)bz * ((long long)CC * NN);
    }

    int m0 = blockIdx.y * 128;
    int n0 = blockIdx.x * 128;
    int t = threadIdx.x;
    int lane = t & 31;
    int wid = t >> 5;
    int wm0 = (wid & 3) * 32;
    int wn0 = (wid >> 2) * 64;

    float acc[2][8][4];
    #pragma unroll
    for (int mi = 0; mi < 2; mi++)
        #pragma unroll
        for (int ni = 0; ni < 8; ni++)
            #pragma unroll
            for (int j = 0; j < 4; j++) acc[mi][ni][j] = 0.f;

    int ktot = K >> 5;
    int lrow0 = t >> 2;
    int lch = (t & 3) * 8;

    {
        #pragma unroll
        for (int p = 0; p < 2; p++) {
            int row = lrow0 + p * 64;
            cp16(&sAt[0][row * SPITCH + lch], A + (size_t)(m0 + row) * lda + lch);
            cp16(&sBt[0][row * SPITCH + lch], B + (size_t)(n0 + row) * ldb + lch);
        }
        cp_commit();
    }

    for (int kt = 0; kt < ktot; kt++) {
        int buf = kt & 1;
        if (kt + 1 < ktot) {
            int nb = buf ^ 1;
            int k0 = (kt + 1) << 5;
            #pragma unroll
            for (int p = 0; p < 2; p++) {
                int row = lrow0 + p * 64;
                cp16(&sAt[nb][row * SPITCH + lch], A + (size_t)(m0 + row) * lda + k0 + lch);
                cp16(&sBt[nb][row * SPITCH + lch], B + (size_t)(n0 + row) * ldb + k0 + lch);
            }
            cp_commit();
            cp_wait<1>();
        } else {
            cp_wait<0>();
        }
        __syncthreads();

        uint32_t baseA = s2u(&sAt[buf][0]);
        uint32_t baseB = s2u(&sBt[buf][0]);
        #pragma unroll
        for (int h = 0; h < 2; h++) {
            int kk = h * 16;
            uint32_t a[2][4];
            #pragma unroll
            for (int mi = 0; mi < 2; mi++) {
                int row = wm0 + mi * 16 + (lane & 15);
                int col = kk + ((lane >> 4) << 3);
                ldsm4(a[mi][0], a[mi][1], a[mi][2], a[mi][3],
                      baseA + (row * SPITCH + col) * 2);
            }
            uint32_t bf[8][2];
            #pragma unroll
            for (int nj = 0; nj < 4; nj++) {
                int seg = lane >> 3, r = lane & 7;
                int n = wn0 + nj * 16 + ((seg >> 1) << 3) + r;
                int col = kk + ((seg & 1) << 3);
                uint32_t r0, r1, r2, r3;
                ldsm4(r0, r1, r2, r3, baseB + (n * SPITCH + col) * 2);
                bf[2 * nj][0] = r0; bf[2 * nj][1] = r1;
                bf[2 * nj + 1][0] = r2; bf[2 * nj + 1][1] = r3;
            }
            #pragma unroll
            for (int mi = 0; mi < 2; mi++)
                #pragma unroll
                for (int ni = 0; ni < 8; ni++)
                    mma16816(acc[mi][ni], a[mi], bf[ni]);
        }
        __syncthreads();
    }

    #pragma unroll
    for (int mi = 0; mi < 2; mi++) {
        int r0 = m0 + wm0 + mi * 16 + (lane >> 2);
        float b0 = bias[r0], b8 = bias[r0 + 8];
        #pragma unroll
        for (int ni = 0; ni < 8; ni++) {
            int c = n0 + wn0 + ni * 8 + 2 * (lane & 3);
            if (OUTMODE == 2) {
                float2 ra = *(const float2*)&res[(size_t)r0 * ldc + c];
                float2 rb = *(const float2*)&res[(size_t)(r0 + 8) * ldc + c];
                float2 v01 = make_float2(acc[mi][ni][0] + b0 + ra.x, acc[mi][ni][1] + b0 + ra.y);
                float2 v23 = make_float2(acc[mi][ni][2] + b8 + rb.x, acc[mi][ni][3] + b8 + rb.y);
                *(float2*)&Cf[(size_t)r0 * ldc + c] = v01;
                *(float2*)&Cf[(size_t)(r0 + 8) * ldc + c] = v23;
            } else {
                float v0 = acc[mi][ni][0] + b0;
                float v1 = acc[mi][ni][1] + b0;
                float v2 = acc[mi][ni][2] + b8;
                float v3 = acc[mi][ni][3] + b8;
                if (r0 < 512) {
                    out_qk[(size_t)c * 512 + r0] = __float2bfloat16(v0);
                    out_qk[(size_t)(c + 1) * 512 + r0] = __float2bfloat16(v1);
                    out_qk[(size_t)c * 512 + r0 + 8] = __float2bfloat16(v2);
                    out_qk[(size_t)(c + 1) * 512 + r0 + 8] = __float2bfloat16(v3);
                } else {
                    *(__nv_bfloat162*)&out_v[(size_t)(r0 - 512) * NN + c] =
                        __floats2bfloat162_rn(v0, v1);
                    *(__nv_bfloat162*)&out_v[(size_t)(r0 - 512 + 8) * NN + c] =
                        __floats2bfloat162_rn(v2, v3);
                }
            }
        }
    }
}

// ---------------------------------------------------------------------------
// Flash attention: one CTA per (q-tile 128, batch). 8 warps x 16 q-rows.
// Q resident in smem; KV streamed in 64-token double-buffered tiles.
// S fragments -> online softmax in registers -> bf16 P fragments -> PV mma.
// ---------------------------------------------------------------------------
#define SM_Q   0
#define SM_K   (128 * QP)
#define SM_V   (SM_K + 2 * 64 * QP)
#define SMEM_FLASH ((SM_V + 2 * 256 * VP) * 2)

__global__ __launch_bounds__(256, 1) void flash_kernel(
    const __nv_bfloat16* __restrict__ qk,   // [b][n][512]
    const __nv_bfloat16* __restrict__ v,    // [b][c][n]
    __nv_bfloat16* __restrict__ Ob) {       // [b][n][256]
    extern __shared__ __nv_bfloat16 sm[];
    __nv_bfloat16* sQ = sm + SM_Q;
    __nv_bfloat16* sK = sm + SM_K;
    __nv_bfloat16* sV = sm + SM_V;

    int batch = blockIdx.y;
    int q0 = blockIdx.x * TQ;
    qk += (size_t)batch * NN * 512;
    v  += (size_t)batch * CC * NN;
    Ob += (size_t)batch * NN * CC;

    int t = threadIdx.x;
    int lane = t & 31;
    int wid = t >> 5;

    // Load Q tile (128 x 256)
    #pragma unroll
    for (int i = 0; i < 16; i++) {
        int id = t + i * 256;
        int row = id >> 5, c8 = (id & 31) * 8;
        cp16(&sQ[row * QP + c8], qk + (size_t)(q0 + row) * 512 + c8);
    }
    cp_commit();

    // KV stage loader
    auto load_kv = [&](int it, int buf) {
        int kv0 = it * TK;
        __nv_bfloat16* kb = sK + buf * 64 * QP;
        __nv_bfloat16* vb = sV + buf * 256 * VP;
        #pragma unroll
        for (int i = 0; i < 8; i++) {
            int id = t + i * 256;
            int row = id >> 5, c8 = (id & 31) * 8;
            cp16(&kb[row * QP + c8], qk + (size_t)(kv0 + row) * 512 + 256 + c8);
        }
        #pragma unroll
        for (int i = 0; i < 8; i++) {
            int id = t + i * 256;
            int row = id >> 3, t8 = (id & 7) * 8;
            cp16(&vb[row * VP + t8], v + (size_t)row * NN + kv0 + t8);
        }
    };

    load_kv(0, 0);
    cp_commit();

    float m0 = -1e30f, m1 = -1e30f, l0 = 0.f, l1 = 0.f;
    float oacc[32][4];
    #pragma unroll
    for (int i = 0; i < 32; i++)
        #pragma unroll
        for (int j = 0; j < 4; j++) oacc[i][j] = 0.f;

    const float SC = 0.0625f;
    int seg = lane >> 3, rr = lane & 7;

    for (int it = 0; it < NIT; it++) {
        int buf = it & 1;
        if (it + 1 < NIT) {
            load_kv(it + 1, buf ^ 1);
            cp_commit();
            cp_wait<1>();
        } else {
            cp_wait<0>();
        }
        __syncthreads();

        uint32_t baseQ = s2u(sQ);
        uint32_t baseK = s2u(sK + buf * 64 * QP);
        uint32_t baseV = s2u(sV + buf * 256 * VP);

        // --- S = Q K^T  (warp: 16 q-rows x 64 kv) ---
        float sacc[8][4];
        #pragma unroll
        for (int i = 0; i < 8; i++)
            #pragma unroll
            for (int j = 0; j < 4; j++) sacc[i][j] = 0.f;

        int arow = wid * 16 + (lane & 15);
        int acolo = (lane >> 4) << 3;
        #pragma unroll
        for (int k = 0; k < 16; k++) {
            uint32_t a[4];
            ldsm4(a[0], a[1], a[2], a[3], baseQ + (arow * QP + k * 16 + acolo) * 2);
            #pragma unroll
            for (int nj = 0; nj < 4; nj++) {
                int n = nj * 16 + ((seg >> 1) << 3) + rr;
                int col = k * 16 + ((seg & 1) << 3);
                uint32_t b0, b1, b2, b3;
                ldsm4(b0, b1, b2, b3, baseK + (n * QP + col) * 2);
                uint32_t bb0[2] = {b0, b1}, bb1[2] = {b2, b3};
                mma16816(sacc[2 * nj], a, bb0);
                mma16816(sacc[2 * nj + 1], a, bb1);
            }
        }

        // --- online softmax on fragments ---
        float tm0 = -1e30f, tm1 = -1e30f;
        #pragma unroll
        for (int ns = 0; ns < 8; ns++) {
            tm0 = fmaxf(tm0, fmaxf(sacc[ns][0], sacc[ns][1]));
            tm1 = fmaxf(tm1, fmaxf(sacc[ns][2], sacc[ns][3]));
        }
        tm0 = fmaxf(tm0, __shfl_xor_sync(0xffffffffu, tm0, 1));
        tm0 = fmaxf(tm0, __shfl_xor_sync(0xffffffffu, tm0, 2));
        tm1 = fmaxf(tm1, __shfl_xor_sync(0xffffffffu, tm1, 1));
        tm1 = fmaxf(tm1, __shfl_xor_sync(0xffffffffu, tm1, 2));

        float m0n = fmaxf(m0, tm0 * SC);
        float m1n = fmaxf(m1, tm1 * SC);
        float sc0 = __expf(m0 - m0n);
        float sc1 = __expf(m1 - m1n);
        m0 = m0n; m1 = m1n;

        float sum0 = 0.f, sum1 = 0.f;
        uint32_t pf[4][4];
        #pragma unroll
        for (int j = 0; j < 4; j++) {
            float p00 = __expf(sacc[2 * j][0] * SC - m0);
            float p01 = __expf(sacc[2 * j][1] * SC - m0);
            float p02 = __expf(sacc[2 * j][2] * SC - m1);
            float p03 = __expf(sacc[2 * j][3] * SC - m1);
            float p10 = __expf(sacc[2 * j + 1][0] * SC - m0);
            float p11 = __expf(sacc[2 * j + 1][1] * SC - m0);
            float p12 = __expf(sacc[2 * j + 1][2] * SC - m1);
            float p13 = __expf(sacc[2 * j + 1][3] * SC - m1);
            sum0 += p00 + p01 + p10 + p11;
            sum1 += p02 + p03 + p12 + p13;
            pf[j][0] = packbf(p00, p01);
            pf[j][1] = packbf(p02, p03);
            pf[j][2] = packbf(p10, p11);
            pf[j][3] = packbf(p12, p13);
        }
        sum0 += __shfl_xor_sync(0xffffffffu, sum0, 1);
        sum0 += __shfl_xor_sync(0xffffffffu, sum0, 2);
        sum1 += __shfl_xor_sync(0xffffffffu, sum1, 1);
        sum1 += __shfl_xor_sync(0xffffffffu, sum1, 2);
        l0 = l0 * sc0 + sum0;
        l1 = l1 * sc1 + sum1;

        #pragma unroll
        for (int ns = 0; ns < 32; ns++) {
            oacc[ns][0] *= sc0; oacc[ns][1] *= sc0;
            oacc[ns][2] *= sc1; oacc[ns][3] *= sc1;
        }

        // --- O += P V  (k = 64 tokens, n = 256 channels) ---
        #pragma unroll
        for (int j = 0; j < 4; j++) {
            #pragma unroll
            for (int nj = 0; nj < 16; nj++) {
                int n = nj * 16 + ((seg >> 1) << 3) + rr;
                int col = j * 16 + ((seg & 1) << 3);
                uint32_t b0, b1, b2, b3;
                ldsm4(b0, b1, b2, b3, baseV + (n * VP + col) * 2);
                uint32_t bb0[2] = {b0, b1}, bb1[2] = {b2, b3};
                mma16816(oacc[2 * nj], pf[j], bb0);
                mma16816(oacc[2 * nj + 1], pf[j], bb1);
            }
        }
        __syncthreads();
    }

    // epilogue: normalize, write bf16 [q, c]
    float inv0 = 1.f / l0;
    float inv1 = 1.f / l1;
    int qr = q0 + wid * 16 + (lane >> 2);
    #pragma unroll
    for (int ns = 0; ns < 32; ns++) {
        int c = ns * 8 + 2 * (lane & 3);
        *(__nv_bfloat162*)&Ob[(size_t)qr * CC + c] =
            __floats2bfloat162_rn(oacc[ns][0] * inv0, oacc[ns][1] * inv0);
        *(__nv_bfloat162*)&Ob[(size_t)(qr + 8) * CC + c] =
            __floats2bfloat162_rn(oacc[ns][2] * inv1, oacc[ns][3] * inv1);
    }
}

// ---------------------------------------------------------------------------
extern "C" void kernel_launch(void* const* d_in, const int* in_sizes, int n_in,
                              void* d_out, int out_size) {
    const float* x  = (const float*)d_in[0];
    const float* nw = (const float*)d_in[1];
    const float* nb = (const float*)d_in[2];
    const float* qw = (const float*)d_in[3];
    const float* qb = (const float*)d_in[4];
    const float* pw = (const float*)d_in[5];
    const float* pb = (const float*)d_in[6];
    float* out = (float*)d_out;

    __nv_bfloat16 *hTP, *qkTP, *vP, *ObP, *wqP, *wpP;
    cudaGetSymbolAddress((void**)&hTP, g_hT);
    cudaGetSymbolAddress((void**)&qkTP, g_qkT);
    cudaGetSymbolAddress((void**)&vP, g_v);
    cudaGetSymbolAddress((void**)&ObP, g_Ob);
    cudaGetSymbolAddress((void**)&wqP, g_wqkv);
    cudaGetSymbolAddress((void**)&wpP, g_wproj);

    const long long sCN = (long long)CC * NN;
    const long long sNC = (long long)NN * CC;

    cudaFuncSetAttribute(flash_kernel, cudaFuncAttributeMaxDynamicSharedMemorySize,
                         SMEM_FLASH);

    // 0) weights -> bf16
    cvt_w_kernel<<<768, 256>>>(qw, wqP, 768 * 256);
    cvt_w_kernel<<<256, 256>>>(pw, wpP, 256 * 256);

    // 1) GroupNorm -> hT bf16 [n, c]
    gn_kernel<<<BB * GG, 256>>>(x, nw, nb, hTP);

    // 2) qkv: -> qkT [n,512] bf16, v [c,n] bf16
    mma_gemm<1><<<dim3(NN / 128, 768 / 128, BB), 256>>>(
        wqP, hTP, qb, (const float*)0, (float*)0, qkTP, vP,
        768, NN, CC, CC, CC, 0, 0LL, sNC, 0LL, 0LL);

    // 3) flash attention -> Ob [n, c] bf16
    flash_kernel<<<dim3(NN / TQ, BB), 256, SMEM_FLASH>>>(qkTP, vP, ObP);

    // 4) out = x + proj_w @ O + proj_b   (bf16 mma, fp32 residual epilogue)
    mma_gemm<2><<<dim3(NN / 128, CC / 128, BB), 256>>>(
        wpP, ObP, pb, x, out, (__nv_bfloat16*)0, (__nv_bfloat16*)0,
        CC, NN, CC, CC, CC, NN, 0LL, sNC, sCN, sCN);
}